// round 3
// baseline (speedup 1.0000x reference)
#include <cuda_runtime.h>
#include <math.h>

#define NB 32768

// ---------------- device scratch (static; no allocations) ----------------
static __device__ float    g_w1s[2048*64];                        // sign(w1) fp32
static __device__ unsigned g_p2[1024*64], g_z2[1024*64], g_f2[1024];
static __device__ unsigned g_p3[512*32],  g_z3[512*32],  g_f3[512];
static __device__ unsigned g_p4[64*16],   g_z4[64*16],   g_f4[64];
static __device__ unsigned g_h1[NB*64];   // layer1 bits (2048/row)
static __device__ unsigned g_h2[NB*32];   // layer2 bits (1024/row)
static __device__ unsigned g_h3[NB*16];   // layer3 bits (512/row)

// ---------------- prep: sign(w1) as floats ----------------
__global__ void prep_sign_k(const float* __restrict__ w1) {
    int i = blockIdx.x * 256 + threadIdx.x;
    if (i < 2048*64) {
        float w = w1[i];
        g_w1s[i] = (w > 0.f) ? 1.f : ((w < 0.f) ? -1.f : 0.f);
    }
}

// ---------------- prep: P/Z masks + zero-flag, warp-ballot (coalesced) ----------------
template<int L>
__global__ void prep_pz_k(const float* __restrict__ w) {
    constexpr int OUT = (L==2) ? 1024 : (L==3) ? 512 : 64;
    constexpr int INW = (L==2) ? 64   : (L==3) ? 32  : 16;
    unsigned* __restrict__ P = (L==2) ? g_p2 : (L==3) ? g_p3 : g_p4;
    unsigned* __restrict__ Z = (L==2) ? g_z2 : (L==3) ? g_z3 : g_z4;
    unsigned* __restrict__ F = (L==2) ? g_f2 : (L==3) ? g_f3 : g_f4;
    int warp = (blockIdx.x * 256 + threadIdx.x) >> 5;
    int lane = threadIdx.x & 31;
    if (warp >= OUT) return;
    const float* row = w + (size_t)warp * (INW * 32);
    unsigned f = 0;
    for (int wd = 0; wd < INW; wd++) {
        float v = row[wd*32 + lane];
        unsigned p = __ballot_sync(0xffffffffu, v > 0.f);
        unsigned z = __ballot_sync(0xffffffffu, v == 0.f);
        if (lane == 0) { P[(size_t)warp*INW + wd] = p; Z[(size_t)warp*INW + wd] = z; }
        f |= z;
    }
    if (lane == 0) F[warp] = f;
}

// ---------------- layer 1: fp32 GEMM (strict seq-k fma) + threshold + pack ----------------
// 128 rows x 64 cols per CTA, 256 threads, 8x4 register tile. ws XOR-swizzled.
__global__ __launch_bounds__(256) void layer1_k(
    const float* __restrict__ x,  const float* __restrict__ b1,
    const float* __restrict__ g1, const float* __restrict__ be1,
    const float* __restrict__ m1, const float* __restrict__ v1)
{
    __shared__ float xs[128*64];   // 32 KB (reused as bit staging)
    __shared__ float ws[64*64];    // 16 KB
    const int tid = threadIdx.x;
    const int rb = blockIdx.y * 128;
    const int cb = blockIdx.x * 64;

    {   // x tile: 128x64 contiguous floats
        const float4* xg = (const float4*)(x + (size_t)rb * 64);
        float4* xd = (float4*)xs;
#pragma unroll
        for (int i = 0; i < 8; i++) xd[tid + i*256] = xg[tid + i*256];
    }
    for (int idx = tid; idx < 64*64; idx += 256) {   // w tile, XOR swizzle in k
        int c = idx >> 6, k = idx & 63;
        ws[(c << 6) + (k ^ (c & 31))] = g_w1s[(size_t)cb * 64 + idx];
    }
    __syncthreads();

    const int ty = tid >> 4, tx = tid & 15;
    float acc[8][4];
#pragma unroll
    for (int i = 0; i < 8; i++)
#pragma unroll
        for (int j = 0; j < 4; j++) acc[i][j] = 0.f;

    int wbase[4], wx[4];
#pragma unroll
    for (int j = 0; j < 4; j++) { int c = tx + 16*j; wbase[j] = c << 6; wx[j] = c & 31; }
    const float* xp = xs + (ty * 8) * 64;

#pragma unroll 8
    for (int k = 0; k < 64; k++) {          // STRICT ascending-k fma chains
        float wv[4];
#pragma unroll
        for (int j = 0; j < 4; j++) wv[j] = ws[wbase[j] + (k ^ wx[j])];
#pragma unroll
        for (int i = 0; i < 8; i++) {
            float xv = xp[i*64 + k];
#pragma unroll
            for (int j = 0; j < 4; j++) acc[i][j] = fmaf(xv, wv[j], acc[i][j]);
        }
    }
    __syncthreads();   // done reading xs; reuse as byte staging

    unsigned char* sbits = (unsigned char*)xs;
    float bb[4], mm[4], sc[4], bee[4];
#pragma unroll
    for (int j = 0; j < 4; j++) {
        int c = cb + tx + 16*j;
        bb[j] = b1[c]; mm[j] = m1[c]; bee[j] = be1[c];
        sc[j] = g1[c] / sqrtf(v1[c] + 1e-5f);
    }
#pragma unroll
    for (int i = 0; i < 8; i++)
#pragma unroll
        for (int j = 0; j < 4; j++) {
            float u = ((acc[i][j] + bb[j]) - mm[j]) * sc[j] + bee[j];
            sbits[(ty*8 + i)*64 + (tx + 16*j)] = (u > 0.f) ? 1 : 0;
        }
    __syncthreads();

    {   // pack 128 rows x 2 words
        int r = tid >> 1, w = tid & 1;
        const unsigned* bp = (const unsigned*)(sbits + r*64 + w*32);
        unsigned bits = 0;
#pragma unroll
        for (int q = 0; q < 8; q++) {
            unsigned u = bp[q];
            bits |= (u         & 1u) << (4*q    );
            bits |= ((u >> 8 ) & 1u) << (4*q + 1);
            bits |= ((u >> 16) & 1u) << (4*q + 2);
            bits |= ((u >> 24) & 1u) << (4*q + 3);
        }
        g_h1[(size_t)(rb + r) * 64 + blockIdx.x * 2 + w] = bits;
    }
}

// ---------------- layers 2/3: popcount GEMM + threshold + pack ----------------
// 64 rows x 64 cols per CTA, 256 threads, 4x4 tile. s = 2*popc(h&P) - cnt (+Z fix).
template<int L>
__global__ __launch_bounds__(256) void binlayer_k(
    const float* __restrict__ b,  const float* __restrict__ g,
    const float* __restrict__ be, const float* __restrict__ m,
    const float* __restrict__ v)
{
    constexpr int INW  = (L==2) ? 64 : 32;
    constexpr int OUT  = (L==2) ? 1024 : 512;
    constexpr int OUTW = OUT / 32;
    constexpr int ST   = INW + 1;
    const unsigned* __restrict__ H  = (L==2) ? g_h1 : g_h2;
    unsigned*       __restrict__ Hn = (L==2) ? g_h2 : g_h3;
    const unsigned* __restrict__ P  = (L==2) ? g_p2 : g_p3;
    const unsigned* __restrict__ Z  = (L==2) ? g_z2 : g_z3;
    const unsigned* __restrict__ F  = (L==2) ? g_f2 : g_f3;

    __shared__ unsigned hs[64*ST];
    __shared__ unsigned ps[64*ST];   // reused as bit staging
    __shared__ int cnt[64];

    const int tid = threadIdx.x;
    const int rb = blockIdx.y * 64, cb = blockIdx.x * 64;

    for (int idx = tid; idx < 64*INW; idx += 256) {
        int r = idx / INW, w = idx % INW;
        hs[r*ST + w] = H[(size_t)rb * INW + idx];
        ps[r*ST + w] = P[(size_t)cb * INW + idx];
    }
    __syncthreads();
    if (tid < 64) {                 // per-row total popcount
        int s = 0;
#pragma unroll 8
        for (int w = 0; w < INW; w++) s += __popc(hs[tid*ST + w]);
        cnt[tid] = s;
    }

    const int ty = tid >> 4, tx = tid & 15;
    int pacc[4][4];
#pragma unroll
    for (int i = 0; i < 4; i++)
#pragma unroll
        for (int j = 0; j < 4; j++) pacc[i][j] = 0;

#pragma unroll 4
    for (int w = 0; w < INW; w++) {
        unsigned hv[4], pv[4];
#pragma unroll
        for (int i = 0; i < 4; i++) hv[i] = hs[(ty*4 + i)*ST + w];
#pragma unroll
        for (int j = 0; j < 4; j++) pv[j] = ps[(tx + 16*j)*ST + w];
#pragma unroll
        for (int i = 0; i < 4; i++)
#pragma unroll
            for (int j = 0; j < 4; j++) pacc[i][j] += __popc(hv[i] & pv[j]);
    }
    __syncthreads();                // cnt visible; ps free for reuse

    unsigned char* sbits = (unsigned char*)ps;
    float bb[4], mm[4], sc[4], bee[4]; unsigned fl[4];
#pragma unroll
    for (int j = 0; j < 4; j++) {
        int c = cb + tx + 16*j;
        bb[j] = b[c]; mm[j] = m[c]; bee[j] = be[c];
        sc[j] = g[c] / sqrtf(v[c] + 1e-5f);
        fl[j] = F[c];
    }
#pragma unroll
    for (int i = 0; i < 4; i++) {
        int cr = cnt[ty*4 + i];
#pragma unroll
        for (int j = 0; j < 4; j++) {
            int s = 2*pacc[i][j] - cr;
            if (fl[j]) {            // rare: exact-zero weights contribute 0, not -1
                int zc = 0;
                const unsigned* zp = Z + (size_t)(cb + tx + 16*j) * INW;
                for (int w = 0; w < INW; w++) zc += __popc(hs[(ty*4+i)*ST + w] & zp[w]);
                s += zc;
            }
            float u = (((float)s + bb[j]) - mm[j]) * sc[j] + bee[j];
            sbits[(ty*4 + i)*64 + (tx + 16*j)] = (u > 0.f) ? 1 : 0;
        }
    }
    __syncthreads();

    if (tid < 128) {                // pack 64 rows x 2 words
        int r = tid >> 1, w = tid & 1;
        const unsigned* bp = (const unsigned*)(sbits + r*64 + w*32);
        unsigned bits = 0;
#pragma unroll
        for (int q = 0; q < 8; q++) {
            unsigned u = bp[q];
            bits |= (u         & 1u) << (4*q    );
            bits |= ((u >> 8 ) & 1u) << (4*q + 1);
            bits |= ((u >> 16) & 1u) << (4*q + 2);
            bits |= ((u >> 24) & 1u) << (4*q + 3);
        }
        Hn[(size_t)(rb + r) * OUTW + blockIdx.x * 2 + w] = bits;
    }
}

// ---------------- fused layer 4 (popcount) + layer 5 (fp32 dot) + sigmoid ----------------
__global__ __launch_bounds__(256) void l4l5_k(
    const float* __restrict__ b4, const float* __restrict__ g4,
    const float* __restrict__ be4,const float* __restrict__ m4,
    const float* __restrict__ v4, const float* __restrict__ w5,
    const float* __restrict__ b5, float* __restrict__ out)
{
    __shared__ unsigned P4s[64*16], Z4s[64*16];
    __shared__ unsigned F4s[64];
    __shared__ float w5s[64], tb[64], tm[64], tsc[64], tbe[64];
    const int tid = threadIdx.x;

    for (int i = tid; i < 64*16; i += 256) { P4s[i] = g_p4[i]; Z4s[i] = g_z4[i]; }
    if (tid < 64) {
        F4s[tid] = g_f4[tid];
        w5s[tid] = w5[tid];
        tb[tid] = b4[tid]; tm[tid] = m4[tid]; tbe[tid] = be4[tid];
        tsc[tid] = g4[tid] / sqrtf(v4[tid] + 1e-5f);
    }
    __syncthreads();

    const int r = blockIdx.x * 256 + tid;
    unsigned h[16];
    const uint4* hp = (const uint4*)(g_h3 + (size_t)r * 16);
#pragma unroll
    for (int q = 0; q < 4; q++) {
        uint4 t = hp[q];
        h[4*q] = t.x; h[4*q+1] = t.y; h[4*q+2] = t.z; h[4*q+3] = t.w;
    }
    int cnt = 0;
#pragma unroll
    for (int w = 0; w < 16; w++) cnt += __popc(h[w]);

    float acc = 0.f;                 // ascending-c order matches h @ w5.T (zero terms exact)
    for (int c = 0; c < 64; c++) {
        int pc = 0;
#pragma unroll
        for (int w = 0; w < 16; w++) pc += __popc(h[w] & P4s[c*16 + w]);
        int s = 2*pc - cnt;
        if (F4s[c]) {
            int zc = 0;
#pragma unroll
            for (int w = 0; w < 16; w++) zc += __popc(h[w] & Z4s[c*16 + w]);
            s += zc;
        }
        float u = (((float)s + tb[c]) - tm[c]) * tsc[c] + tbe[c];
        if (u > 0.f) acc += w5s[c];
    }
    float t = acc + b5[0];
    out[r] = 1.f / (1.f + expf(-t));
}

// ---------------- launch ----------------
extern "C" void kernel_launch(void* const* d_in, const int* in_sizes, int n_in,
                              void* d_out, int out_size) {
    const float* x   = (const float*)d_in[0];
    const float* w1  = (const float*)d_in[1];
    const float* b1  = (const float*)d_in[2];
    const float* w2  = (const float*)d_in[3];
    const float* b2  = (const float*)d_in[4];
    const float* w3  = (const float*)d_in[5];
    const float* b3  = (const float*)d_in[6];
    const float* w4  = (const float*)d_in[7];
    const float* b4  = (const float*)d_in[8];
    const float* w5  = (const float*)d_in[9];
    const float* b5  = (const float*)d_in[10];
    const float* g1  = (const float*)d_in[11];
    const float* be1 = (const float*)d_in[12];
    const float* m1  = (const float*)d_in[13];
    const float* v1  = (const float*)d_in[14];
    const float* g2  = (const float*)d_in[15];
    const float* be2 = (const float*)d_in[16];
    const float* m2  = (const float*)d_in[17];
    const float* v2  = (const float*)d_in[18];
    const float* g3  = (const float*)d_in[19];
    const float* be3 = (const float*)d_in[20];
    const float* m3  = (const float*)d_in[21];
    const float* v3  = (const float*)d_in[22];
    const float* g4  = (const float*)d_in[23];
    const float* be4 = (const float*)d_in[24];
    const float* m4  = (const float*)d_in[25];
    const float* v4  = (const float*)d_in[26];
    float* out = (float*)d_out;

    prep_sign_k<<<512, 256>>>(w1);
    prep_pz_k<2><<<128, 256>>>(w2);
    prep_pz_k<3><<<64, 256>>>(w3);
    prep_pz_k<4><<<8, 256>>>(w4);

    layer1_k<<<dim3(32, 256), 256>>>(x, b1, g1, be1, m1, v1);
    binlayer_k<2><<<dim3(16, 512), 256>>>(b2, g2, be2, m2, v2);
    binlayer_k<3><<<dim3(8, 512), 256>>>(b3, g3, be3, m3, v3);
    l4l5_k<<<128, 256>>>(b4, g4, be4, m4, v4, w5, b5, out);
}